// round 7
// baseline (speedup 1.0000x reference)
#include <cuda_runtime.h>
#include <cuda_bf16.h>

// RLFrameSelector via warp-level bf16 mma.sync (sm_80-class PTX only; the
// harness targets plain sm_103 so tcgen05/arch-'a' instructions are
// unavailable). scores = relu(x@W1+b1)@W2+b2 computed with a 6-product
// 3-way bf16 split (error ~2^-26, below fp32 reorder noise), mask, exact
// top-k, gather.  B=32, T=2048, F=512, U=128, M=65536.

#define NEG_BIG -1.0e9f

__device__ float g_scores[65536];
__device__ unsigned char g_flags[65536];
// W1 split h/m/l, transposed to [split][u=128][k=512] bf16, packed as uint4
// (8 k-values). uint4 index = (s*128 + n)*64 + kg,  kg = k/8.
__device__ uint4 g_w[3 * 128 * 64];

// ---------------------------------------------------------------- helpers --
__device__ __forceinline__ unsigned smem_u32(const void* p) {
    return (unsigned)__cvta_generic_to_shared(p);
}
__device__ __forceinline__ void cp_async16(unsigned dst, const void* src) {
    asm volatile("cp.async.cg.shared.global [%0], [%1], 16;" :: "r"(dst), "l"(src));
}
__device__ __forceinline__ void ldsm4(unsigned &r0, unsigned &r1,
                                      unsigned &r2, unsigned &r3, unsigned a) {
    asm volatile("ldmatrix.sync.aligned.m8n8.x4.shared.b16 {%0,%1,%2,%3}, [%4];"
                 : "=r"(r0), "=r"(r1), "=r"(r2), "=r"(r3) : "r"(a));
}
__device__ __forceinline__ void mma_bf16(float &c0, float &c1, float &c2, float &c3,
                                         unsigned a0, unsigned a1, unsigned a2,
                                         unsigned a3, unsigned b0, unsigned b1) {
    asm volatile(
        "mma.sync.aligned.m16n8k16.row.col.f32.bf16.bf16.f32 "
        "{%0,%1,%2,%3}, {%4,%5,%6,%7}, {%8,%9}, {%0,%1,%2,%3};"
        : "+f"(c0), "+f"(c1), "+f"(c2), "+f"(c3)
        : "r"(a0), "r"(a1), "r"(a2), "r"(a3), "r"(b0), "r"(b1));
}
__device__ __forceinline__ void split3(float v, float &h, float &m, float &l) {
    h = __bfloat162float(__float2bfloat16_rn(v));
    float r = v - h;
    m = __bfloat162float(__float2bfloat16_rn(r));
    l = r - m;   // rounded at pack time
}
__device__ __forceinline__ unsigned packbf(float a, float b) {
    __nv_bfloat162 t = __floats2bfloat162_rn(a, b);
    return *(unsigned*)&t;
}

// smem layout (bytes), rows are 80B-strided (32 bf16 + 16B pad: conflict-free
// for ldmatrix 8-row phases and 16B-granular STS):
//   A  : 3 splits x 128 x 80          = 30720
//   B  : 2 bufs x 3 splits x 128 x 80 = 61440
//   sB1: 512   sW2: 512   red: 1024   rednz: 1024
#define A_OFF    0
#define B_OFF    30720
#define SB1_OFF  92160
#define SW2_OFF  92672
#define RED_OFF  93184
#define RNZ_OFF  94208
#define SMEM_BYTES 95232
#define SPLIT_STRIDE 10240
#define BBUF_STRIDE  30720

// ---------------------------------------------------------------------------
// W prep: split W1[k=512][u=128] into h/m/l bf16, write transposed [s][u][k].
// ---------------------------------------------------------------------------
__global__ void wprep_kernel(const float* __restrict__ W1) {
    int g = blockIdx.x * 256 + threadIdx.x;
    if (g >= 3 * 64 * 128) return;
    int s = g >> 13;            // /8192
    int rem = g & 8191;
    int kg = rem >> 7;
    int n = rem & 127;
    unsigned w[4];
#pragma unroll
    for (int q = 0; q < 4; q++) {
        float sp[2][3];
#pragma unroll
        for (int t = 0; t < 2; t++) {
            float v = W1[(kg * 8 + q * 2 + t) * 128 + n];
            split3(v, sp[t][0], sp[t][1], sp[t][2]);
        }
        w[q] = packbf(sp[0][s], sp[1][s]);
    }
    uint4 u; u.x = w[0]; u.y = w[1]; u.z = w[2]; u.w = w[3];
    g_w[(s * 128 + n) * 64 + kg] = u;
}

// ---------------------------------------------------------------------------
// Kernel A: 6-product bf16-split GEMM on mma.sync + fused relu/W2/mask.
// CTA = 128 frames x 128 U, 512 threads (16 warps), warp tile 16x64.
// K chunks of 32; B double-buffered via cp.async, A rebuilt from LDG regs.
// ---------------------------------------------------------------------------
__global__ __launch_bounds__(512, 1) void score_kernel(
    const float* __restrict__ x, const float* __restrict__ b1,
    const float* __restrict__ W2, const float* __restrict__ b2)
{
    extern __shared__ char smc[];
    const unsigned smb = smem_u32(smc);
    float* sB1 = (float*)(smc + SB1_OFF);
    float* sW2 = (float*)(smc + SW2_OFF);
    float* red = (float*)(smc + RED_OFF);
    unsigned* rnz = (unsigned*)(smc + RNZ_OFF);

    const int tid = threadIdx.x;
    const int w = tid >> 5;
    const int l = tid & 31;
    const int bm0 = blockIdx.x << 7;

    if (tid < 128) { sB1[tid] = b1[tid]; sW2[tid] = W2[tid]; }

    // per-thread x staging: row = tid>>2 (0..127), kg = tid&3 (8 k each)
    const int arow = tid >> 2, akg = tid & 3;
    const float4* xg4 = (const float4*)x + (size_t)(bm0 + arow) * 128 + akg * 2;

    float4 xr0, xr1;
    xr0 = xg4[0]; xr1 = xg4[1];                       // chunk 0

    auto load_B = [&](int c) {
        unsigned base = smb + B_OFF + (unsigned)((c & 1) * BBUF_STRIDE);
#pragma unroll
        for (int p = 0; p < 3; p++) {
            int e = tid + p * 512;
            int s = e >> 9, i = e & 511;
            int n = i >> 2, j = i & 3;
            cp_async16(base + s * SPLIT_STRIDE + n * 80 + j * 16,
                       &g_w[(s * 128 + n) * 64 + c * 4 + j]);
        }
        asm volatile("cp.async.commit_group;" ::: "memory");
    };
    load_B(0);

    float acc[8][4];
#pragma unroll
    for (int nt = 0; nt < 8; nt++)
#pragma unroll
        for (int q = 0; q < 4; q++) acc[nt][q] = 0.f;

    const int mrow0 = (w & 7) * 16;
    const int nb0 = (w >> 3) * 64;
    // A ldmatrix base address (per split/kstep added later)
    const unsigned a_lm = smb + A_OFF + (mrow0 + (l & 15)) * 80 + (l >> 4) * 16;
    const unsigned b_lm_row = (l & 7) * 80 + (l >> 3) * 16;

    for (int c = 0; c < 16; c++) {
        __syncthreads();   // A free (prev ldmatrix done), B buf^1 consumed
        // convert current x regs -> 3 bf16 A tiles (one STS.128 per split)
        {
            float v[8] = {xr0.x, xr0.y, xr0.z, xr0.w, xr1.x, xr1.y, xr1.z, xr1.w};
            char* ab = smc + A_OFF + arow * 80 + akg * 16;
            uint4 hw, mw, lw;
            unsigned* hp = (unsigned*)&hw;
            unsigned* mp = (unsigned*)&mw;
            unsigned* lp = (unsigned*)&lw;
#pragma unroll
            for (int q = 0; q < 4; q++) {
                float h0, m0, l0, h1, m1, l1;
                split3(v[2 * q], h0, m0, l0);
                split3(v[2 * q + 1], h1, m1, l1);
                hp[q] = packbf(h0, h1);
                mp[q] = packbf(m0, m1);
                lp[q] = packbf(l0, l1);
            }
            *(uint4*)(ab)                    = hw;
            *(uint4*)(ab + SPLIT_STRIDE)     = mw;
            *(uint4*)(ab + 2 * SPLIT_STRIDE) = lw;
        }
        if (c + 1 < 16) {
            load_B(c + 1);
            xr0 = xg4[(c + 1) * 8];          // float4 index: chunk stride 32/4
            xr1 = xg4[(c + 1) * 8 + 1];
            asm volatile("cp.async.wait_group 1;" ::: "memory");
        } else {
            asm volatile("cp.async.wait_group 0;" ::: "memory");
        }
        __syncthreads();

        // --- compute chunk c ---
        unsigned a[6][4];
#pragma unroll
        for (int s = 0; s < 3; s++)
#pragma unroll
            for (int ks = 0; ks < 2; ks++)
                ldsm4(a[s * 2 + ks][0], a[s * 2 + ks][1], a[s * 2 + ks][2],
                      a[s * 2 + ks][3], a_lm + s * SPLIT_STRIDE + ks * 32);

        const unsigned bbase = smb + B_OFF + (unsigned)((c & 1) * BBUF_STRIDE);
#pragma unroll
        for (int nt = 0; nt < 8; nt++) {
            unsigned b[3][4];
#pragma unroll
            for (int s = 0; s < 3; s++)
                ldsm4(b[s][0], b[s][1], b[s][2], b[s][3],
                      bbase + s * SPLIT_STRIDE + (nb0 + nt * 8) * 80 + b_lm_row);
            float* cA = acc[nt];
#pragma unroll
            for (int ks = 0; ks < 2; ks++) {
                unsigned* ah = a[0 * 2 + ks];
                unsigned* am = a[1 * 2 + ks];
                unsigned* al = a[2 * 2 + ks];
                unsigned bh0 = b[0][ks * 2], bh1 = b[0][ks * 2 + 1];
                unsigned bm0r = b[1][ks * 2], bm1 = b[1][ks * 2 + 1];
                unsigned bl0 = b[2][ks * 2], bl1 = b[2][ks * 2 + 1];
                mma_bf16(cA[0], cA[1], cA[2], cA[3], ah[0], ah[1], ah[2], ah[3], bh0, bh1); // hh
                mma_bf16(cA[0], cA[1], cA[2], cA[3], ah[0], ah[1], ah[2], ah[3], bm0r, bm1); // hm
                mma_bf16(cA[0], cA[1], cA[2], cA[3], am[0], am[1], am[2], am[3], bh0, bh1); // mh
                mma_bf16(cA[0], cA[1], cA[2], cA[3], am[0], am[1], am[2], am[3], bm0r, bm1); // mm
                mma_bf16(cA[0], cA[1], cA[2], cA[3], ah[0], ah[1], ah[2], ah[3], bl0, bl1); // hl
                mma_bf16(cA[0], cA[1], cA[2], cA[3], al[0], al[1], al[2], al[3], bh0, bh1); // lh
            }
        }
    }

    // --- epilogue: relu + W2 dot + nz mask, per-row reduce ---
    float p0 = 0.f, p1 = 0.f;
    unsigned nz0 = 0, nz1 = 0;
#pragma unroll
    for (int nt = 0; nt < 8; nt++) {
        int u0 = nb0 + nt * 8 + 2 * (l & 3);
        float ba = sB1[u0], bb = sB1[u0 + 1];
        float wa = sW2[u0], wb = sW2[u0 + 1];
        nz0 |= __float_as_uint(acc[nt][0]) | __float_as_uint(acc[nt][1]);
        nz1 |= __float_as_uint(acc[nt][2]) | __float_as_uint(acc[nt][3]);
        p0 += fmaxf(acc[nt][0] + ba, 0.f) * wa + fmaxf(acc[nt][1] + bb, 0.f) * wb;
        p1 += fmaxf(acc[nt][2] + ba, 0.f) * wa + fmaxf(acc[nt][3] + bb, 0.f) * wb;
    }
#pragma unroll
    for (int d = 1; d <= 2; d <<= 1) {
        p0 += __shfl_xor_sync(0xFFFFFFFFu, p0, d);
        p1 += __shfl_xor_sync(0xFFFFFFFFu, p1, d);
        nz0 |= __shfl_xor_sync(0xFFFFFFFFu, nz0, d);
        nz1 |= __shfl_xor_sync(0xFFFFFFFFu, nz1, d);
    }
    __syncthreads();   // red/rnz smem reuse safe (after compute)
    if ((l & 3) == 0) {
        int half = w >> 3;
        int r0 = mrow0 + (l >> 2), r1 = r0 + 8;
        red[r0 * 2 + half] = p0;  red[r1 * 2 + half] = p1;
        rnz[r0 * 2 + half] = nz0; rnz[r1 * 2 + half] = nz1;
    }
    __syncthreads();
    if (tid < 128) {
        float s = red[tid * 2] + red[tid * 2 + 1] + b2[0];
        unsigned nz = rnz[tid * 2] | rnz[tid * 2 + 1];
        g_scores[bm0 + tid] = nz ? s : NEG_BIG;
    }
}

// ---------------------------------------------------------------------------
// Kernel B: exact top-k per batch row via bitonic sort of (score, ~index).
// ---------------------------------------------------------------------------
__global__ void topk_kernel(const int* kptr) {
    __shared__ unsigned long long sk[2048];
    const int row = blockIdx.x;
    const int tid = threadIdx.x;
    const float* sc = g_scores + row * 2048;

#pragma unroll
    for (int s = 0; s < 2; s++) {
        int t = tid + s * 1024;
        unsigned int u = __float_as_uint(sc[t]);
        u = (u & 0x80000000u) ? ~u : (u | 0x80000000u);
        sk[t] = ((unsigned long long)u << 32) | (unsigned long long)(~(unsigned int)t);
        g_flags[row * 2048 + t] = 0;
    }
    __syncthreads();

    for (int k = 2; k <= 2048; k <<= 1) {
        for (int j = k >> 1; j > 0; j >>= 1) {
#pragma unroll
            for (int s = 0; s < 2; s++) {
                int i = tid + s * 1024;
                int l = i ^ j;
                if (l > i) {
                    unsigned long long a = sk[i], b = sk[l];
                    bool up = ((i & k) == 0);
                    if ((a > b) == up) { sk[i] = b; sk[l] = a; }
                }
            }
            __syncthreads();
        }
    }

    int kk = (kptr != nullptr) ? kptr[0] : 64;
    if (kk < 1) kk = 1;
    if (kk > 2048) kk = 2048;
#pragma unroll
    for (int s = 0; s < 2; s++) {
        int i = tid + s * 1024;
        if (i >= 2048 - kk) {
            unsigned int t = ~(unsigned int)(sk[i] & 0xFFFFFFFFull);
            g_flags[row * 2048 + t] = 1;
        }
    }
}

// ---------------------------------------------------------------------------
// Kernel C: out = flag ? x : 0, grid-stride float4.
// ---------------------------------------------------------------------------
__global__ void output_kernel(const float* __restrict__ x,
                              float* __restrict__ out) {
    const float4* x4 = (const float4*)x;
    float4* o4 = (float4*)out;
    const int stride = gridDim.x * blockDim.x;
    for (int i = blockIdx.x * blockDim.x + threadIdx.x; i < 65536 * 128;
         i += stride) {
        float4 v = make_float4(0.f, 0.f, 0.f, 0.f);
        if (g_flags[i >> 7]) v = x4[i];
        o4[i] = v;
    }
}

extern "C" void kernel_launch(void* const* d_in, const int* in_sizes, int n_in,
                              void* d_out, int out_size) {
    const float* x  = (const float*)d_in[0];
    const float* W1 = (const float*)d_in[1];
    const float* b1 = (const float*)d_in[2];
    const float* W2 = (const float*)d_in[3];
    const float* b2 = (const float*)d_in[4];
    const int* kptr = (n_in >= 6) ? (const int*)d_in[5] : nullptr;

    cudaFuncSetAttribute(score_kernel,
                         cudaFuncAttributeMaxDynamicSharedMemorySize,
                         SMEM_BYTES);
    wprep_kernel<<<96, 256>>>(W1);
    score_kernel<<<512, 512, SMEM_BYTES>>>(x, b1, W2, b2);
    topk_kernel<<<32, 1024>>>(kptr);
    output_kernel<<<2048, 256>>>(x, (float*)d_out);
}

// round 9
// speedup vs baseline: 1.4944x; 1.4944x over previous
#include <cuda_runtime.h>
#include <cuda_fp16.h>

// RLFrameSelector via warp-level fp16 mma.sync (sm_80-class PTX; harness
// targets plain sm_103 so tcgen05 is unavailable). scores =
// relu(x@W1+b1)@W2+b2 with a 3-product 2-way fp16 split (h+l, 22 mantissa
// bits; dropped l*l' ~2^-22 -> score err ~1e-7, far below the top-k
// boundary gap), mask, exact top-k, gather. B=32,T=2048,F=512,U=128.

#define NEG_BIG -1.0e9f

__device__ float g_scores[65536];
__device__ unsigned char g_flags[65536];
// W1 split h/l, transposed to [split][u=128][k=512] fp16 packed as uint4
// (8 k-values). uint4 index = (s*128 + n)*64 + kg, kg = k/8.
__device__ uint4 g_w[2 * 128 * 64];

// ---------------------------------------------------------------- helpers --
__device__ __forceinline__ unsigned smem_u32(const void* p) {
    return (unsigned)__cvta_generic_to_shared(p);
}
__device__ __forceinline__ void cp_async16(unsigned dst, const void* src) {
    asm volatile("cp.async.cg.shared.global [%0], [%1], 16;" :: "r"(dst), "l"(src));
}
__device__ __forceinline__ void ldsm4(unsigned &r0, unsigned &r1,
                                      unsigned &r2, unsigned &r3, unsigned a) {
    asm volatile("ldmatrix.sync.aligned.m8n8.x4.shared.b16 {%0,%1,%2,%3}, [%4];"
                 : "=r"(r0), "=r"(r1), "=r"(r2), "=r"(r3) : "r"(a));
}
__device__ __forceinline__ void mma_f16(float &c0, float &c1, float &c2, float &c3,
                                        unsigned a0, unsigned a1, unsigned a2,
                                        unsigned a3, unsigned b0, unsigned b1) {
    asm volatile(
        "mma.sync.aligned.m16n8k16.row.col.f32.f16.f16.f32 "
        "{%0,%1,%2,%3}, {%4,%5,%6,%7}, {%8,%9}, {%0,%1,%2,%3};"
        : "+f"(c0), "+f"(c1), "+f"(c2), "+f"(c3)
        : "r"(a0), "r"(a1), "r"(a2), "r"(a3), "r"(b0), "r"(b1));
}
__device__ __forceinline__ void split2(float v, float &h, float &l) {
    h = __half2float(__float2half_rn(v));
    l = v - h;    // exact in fp32; rounded to fp16 at pack
}
__device__ __forceinline__ unsigned packh(float a, float b) {
    __half2 t = __floats2half2_rn(a, b);
    return *(unsigned*)&t;
}

// smem layout (bytes), rows 80B-strided (32 fp16 + 16B pad: conflict-free
// for ldmatrix 8-row phases and 16B STS):
//   A  : 2 splits x 128 x 80          = 20480
//   B  : 2 bufs x 2 splits x 128 x 80 = 40960
//   sB1: 512  sW2: 512  red: 1024  rnz: 1024
#define A_OFF    0
#define B_OFF    20480
#define SB1_OFF  61440
#define SW2_OFF  61952
#define RED_OFF  62464
#define RNZ_OFF  63488
#define SMEM_BYTES 64512
#define SPLIT_STRIDE 10240
#define BBUF_STRIDE  20480

// ---------------------------------------------------------------------------
// W prep: split W1[k=512][u=128] into h/l fp16, write transposed [s][u][k].
// ---------------------------------------------------------------------------
__global__ void wprep_kernel(const float* __restrict__ W1) {
    int g = blockIdx.x * 256 + threadIdx.x;
    if (g >= 2 * 64 * 128) return;
    int s = g >> 13;            // /8192
    int rem = g & 8191;
    int kg = rem >> 7;
    int n = rem & 127;
    unsigned w[4];
#pragma unroll
    for (int q = 0; q < 4; q++) {
        float sp[2][2];
#pragma unroll
        for (int t = 0; t < 2; t++) {
            float v = W1[(kg * 8 + q * 2 + t) * 128 + n];
            split2(v, sp[t][0], sp[t][1]);
        }
        w[q] = packh(sp[0][s], sp[1][s]);
    }
    uint4 u; u.x = w[0]; u.y = w[1]; u.z = w[2]; u.w = w[3];
    g_w[(s * 128 + n) * 64 + kg] = u;
}

// ---------------------------------------------------------------------------
// Kernel A: 3-product fp16-split GEMM on mma.sync + fused relu/W2/mask.
// CTA = 128 frames x 128 U, 512 threads (16 warps), warp tile 16x64.
// K chunks of 32; B double-buffered via cp.async, A rebuilt from LDG regs.
// ---------------------------------------------------------------------------
__global__ __launch_bounds__(512, 1) void score_kernel(
    const float* __restrict__ x, const float* __restrict__ b1,
    const float* __restrict__ W2, const float* __restrict__ b2)
{
    extern __shared__ char smc[];
    const unsigned smb = smem_u32(smc);
    float* sB1 = (float*)(smc + SB1_OFF);
    float* sW2 = (float*)(smc + SW2_OFF);
    float* red = (float*)(smc + RED_OFF);
    unsigned* rnz = (unsigned*)(smc + RNZ_OFF);

    const int tid = threadIdx.x;
    const int w = tid >> 5;
    const int l = tid & 31;
    const int bm0 = blockIdx.x << 7;

    if (tid < 128) { sB1[tid] = b1[tid]; sW2[tid] = W2[tid]; }

    // per-thread x staging: row = tid>>2 (0..127), kg = tid&3 (8 k each)
    const int arow = tid >> 2, akg = tid & 3;
    const float4* xg4 = (const float4*)x + (size_t)(bm0 + arow) * 128 + akg * 2;

    float4 xr0 = xg4[0], xr1 = xg4[1];                // chunk 0

    auto load_B = [&](int c) {
        unsigned base = smb + B_OFF + (unsigned)((c & 1) * BBUF_STRIDE);
#pragma unroll
        for (int p = 0; p < 2; p++) {
            int e = tid + p * 512;
            int s = e >> 9, i = e & 511;
            int n = i >> 2, j = i & 3;
            cp_async16(base + s * SPLIT_STRIDE + n * 80 + j * 16,
                       &g_w[(s * 128 + n) * 64 + c * 4 + j]);
        }
        asm volatile("cp.async.commit_group;" ::: "memory");
    };
    load_B(0);

    float acc[8][4];
#pragma unroll
    for (int nt = 0; nt < 8; nt++)
#pragma unroll
        for (int q = 0; q < 4; q++) acc[nt][q] = 0.f;

    const int mrow0 = (w & 7) * 16;
    const int nb0 = (w >> 3) * 64;
    const unsigned a_lm = smb + A_OFF + (mrow0 + (l & 15)) * 80 + (l >> 4) * 16;
    const unsigned b_lm_row = (l & 7) * 80 + (l >> 3) * 16;

    for (int c = 0; c < 16; c++) {
        __syncthreads();   // prev A-ldsm done, prev-prev B buf consumed
        // convert x regs -> 2 fp16 A tiles (one STS.128 per split)
        {
            float v[8] = {xr0.x, xr0.y, xr0.z, xr0.w, xr1.x, xr1.y, xr1.z, xr1.w};
            char* ab = smc + A_OFF + arow * 80 + akg * 16;
            uint4 hw, lw;
            unsigned* hp = (unsigned*)&hw;
            unsigned* lp = (unsigned*)&lw;
#pragma unroll
            for (int q = 0; q < 4; q++) {
                float h0, l0, h1, l1;
                split2(v[2 * q], h0, l0);
                split2(v[2 * q + 1], h1, l1);
                hp[q] = packh(h0, h1);
                lp[q] = packh(l0, l1);
            }
            *(uint4*)(ab)                = hw;
            *(uint4*)(ab + SPLIT_STRIDE) = lw;
        }
        if (c + 1 < 16) {
            load_B(c + 1);
            xr0 = xg4[(c + 1) * 8];
            xr1 = xg4[(c + 1) * 8 + 1];
            asm volatile("cp.async.wait_group 1;" ::: "memory");
        } else {
            asm volatile("cp.async.wait_group 0;" ::: "memory");
        }
        __syncthreads();

        // --- compute chunk c ---
        unsigned a[4][4];   // [split*2+ks][frag]
#pragma unroll
        for (int s = 0; s < 2; s++)
#pragma unroll
            for (int ks = 0; ks < 2; ks++)
                ldsm4(a[s * 2 + ks][0], a[s * 2 + ks][1], a[s * 2 + ks][2],
                      a[s * 2 + ks][3], a_lm + s * SPLIT_STRIDE + ks * 32);

        const unsigned bbase = smb + B_OFF + (unsigned)((c & 1) * BBUF_STRIDE);
#pragma unroll
        for (int nt = 0; nt < 8; nt++) {
            unsigned b[2][4];
#pragma unroll
            for (int s = 0; s < 2; s++)
                ldsm4(b[s][0], b[s][1], b[s][2], b[s][3],
                      bbase + s * SPLIT_STRIDE + (nb0 + nt * 8) * 80 + b_lm_row);
            float* cA = acc[nt];
#pragma unroll
            for (int ks = 0; ks < 2; ks++) {
                unsigned* ah = a[0 * 2 + ks];
                unsigned* al = a[1 * 2 + ks];
                unsigned bh0 = b[0][ks * 2], bh1 = b[0][ks * 2 + 1];
                unsigned bl0 = b[1][ks * 2], bl1 = b[1][ks * 2 + 1];
                mma_f16(cA[0], cA[1], cA[2], cA[3], ah[0], ah[1], ah[2], ah[3], bh0, bh1); // hh
                mma_f16(cA[0], cA[1], cA[2], cA[3], ah[0], ah[1], ah[2], ah[3], bl0, bl1); // hl
                mma_f16(cA[0], cA[1], cA[2], cA[3], al[0], al[1], al[2], al[3], bh0, bh1); // lh
            }
        }
    }

    // --- epilogue: relu + W2 dot + nz mask, per-row reduce ---
    float p0 = 0.f, p1 = 0.f;
    unsigned nz0 = 0, nz1 = 0;
#pragma unroll
    for (int nt = 0; nt < 8; nt++) {
        int u0 = nb0 + nt * 8 + 2 * (l & 3);
        float ba = sB1[u0], bb = sB1[u0 + 1];
        float wa = sW2[u0], wb = sW2[u0 + 1];
        nz0 |= __float_as_uint(acc[nt][0]) | __float_as_uint(acc[nt][1]);
        nz1 |= __float_as_uint(acc[nt][2]) | __float_as_uint(acc[nt][3]);
        p0 += fmaxf(acc[nt][0] + ba, 0.f) * wa + fmaxf(acc[nt][1] + bb, 0.f) * wb;
        p1 += fmaxf(acc[nt][2] + ba, 0.f) * wa + fmaxf(acc[nt][3] + bb, 0.f) * wb;
    }
#pragma unroll
    for (int d = 1; d <= 2; d <<= 1) {
        p0 += __shfl_xor_sync(0xFFFFFFFFu, p0, d);
        p1 += __shfl_xor_sync(0xFFFFFFFFu, p1, d);
        nz0 |= __shfl_xor_sync(0xFFFFFFFFu, nz0, d);
        nz1 |= __shfl_xor_sync(0xFFFFFFFFu, nz1, d);
    }
    __syncthreads();
    if ((l & 3) == 0) {
        int half = w >> 3;
        int r0 = mrow0 + (l >> 2), r1 = r0 + 8;
        red[r0 * 2 + half] = p0;  red[r1 * 2 + half] = p1;
        rnz[r0 * 2 + half] = nz0; rnz[r1 * 2 + half] = nz1;
    }
    __syncthreads();
    if (tid < 128) {
        float s = red[tid * 2] + red[tid * 2 + 1] + b2[0];
        unsigned nz = rnz[tid * 2] | rnz[tid * 2 + 1];
        g_scores[bm0 + tid] = nz ? s : NEG_BIG;
    }
}

// ---------------------------------------------------------------------------
// Kernel B: exact top-k per batch row via bitonic sort of (score, ~index).
// ---------------------------------------------------------------------------
__global__ void topk_kernel(const int* kptr) {
    __shared__ unsigned long long sk[2048];
    const int row = blockIdx.x;
    const int tid = threadIdx.x;
    const float* sc = g_scores + row * 2048;

#pragma unroll
    for (int s = 0; s < 2; s++) {
        int t = tid + s * 1024;
        unsigned int u = __float_as_uint(sc[t]);
        u = (u & 0x80000000u) ? ~u : (u | 0x80000000u);
        sk[t] = ((unsigned long long)u << 32) | (unsigned long long)(~(unsigned int)t);
        g_flags[row * 2048 + t] = 0;
    }
    __syncthreads();

    for (int k = 2; k <= 2048; k <<= 1) {
        for (int j = k >> 1; j > 0; j >>= 1) {
#pragma unroll
            for (int s = 0; s < 2; s++) {
                int i = tid + s * 1024;
                int l = i ^ j;
                if (l > i) {
                    unsigned long long a = sk[i], b = sk[l];
                    bool up = ((i & k) == 0);
                    if ((a > b) == up) { sk[i] = b; sk[l] = a; }
                }
            }
            __syncthreads();
        }
    }

    int kk = (kptr != nullptr) ? kptr[0] : 64;
    if (kk < 1) kk = 1;
    if (kk > 2048) kk = 2048;
#pragma unroll
    for (int s = 0; s < 2; s++) {
        int i = tid + s * 1024;
        if (i >= 2048 - kk) {
            unsigned int t = ~(unsigned int)(sk[i] & 0xFFFFFFFFull);
            g_flags[row * 2048 + t] = 1;
        }
    }
}

// ---------------------------------------------------------------------------
// Kernel C: out = flag ? x : 0, grid-stride float4, streaming stores.
// ---------------------------------------------------------------------------
__global__ void output_kernel(const float* __restrict__ x,
                              float* __restrict__ out) {
    const float4* x4 = (const float4*)x;
    float4* o4 = (float4*)out;
    const int stride = gridDim.x * blockDim.x;
    for (int i = blockIdx.x * blockDim.x + threadIdx.x; i < 65536 * 128;
         i += stride) {
        float4 v = make_float4(0.f, 0.f, 0.f, 0.f);
        if (g_flags[i >> 7]) v = x4[i];
        __stcs(&o4[i], v);
    }
}

extern "C" void kernel_launch(void* const* d_in, const int* in_sizes, int n_in,
                              void* d_out, int out_size) {
    const float* x  = (const float*)d_in[0];
    const float* W1 = (const float*)d_in[1];
    const float* b1 = (const float*)d_in[2];
    const float* W2 = (const float*)d_in[3];
    const float* b2 = (const float*)d_in[4];
    const int* kptr = (n_in >= 6) ? (const int*)d_in[5] : nullptr;

    cudaFuncSetAttribute(score_kernel,
                         cudaFuncAttributeMaxDynamicSharedMemorySize,
                         SMEM_BYTES);
    wprep_kernel<<<64, 256>>>(W1);
    score_kernel<<<512, 512, SMEM_BYTES>>>(x, b1, W2, b2);
    topk_kernel<<<32, 1024>>>(kptr);
    output_kernel<<<2048, 256>>>(x, (float*)d_out);
}

// round 11
// speedup vs baseline: 1.7899x; 1.1978x over previous
#include <cuda_runtime.h>
#include <cuda_fp16.h>

// RLFrameSelector via warp-level fp16 mma.sync. scores = relu(x@W1+b1)@W2+b2
// with a 3-product 2-way fp16 split (h+l, 22 mantissa bits), mask, exact
// top-k, gather. B=32,T=2048,F=512,U=128.
// R10: persistent work-stealing score kernel (M=64 tiles, occ 2) that also
// zero-fills d_out; topk emits a compact selection list; gather rewrites
// only selected frames.

#define NEG_BIG -1.0e9f
#define NTILES 1024

__device__ float g_scores[65536];
__device__ int g_sel[65536];
__device__ int g_tile;
// W1 split h/l, transposed to [split][u=128][k=512] fp16 packed as uint4
// (8 k-values). uint4 index = (s*128 + n)*64 + kg, kg = k/8.
__device__ uint4 g_w[2 * 128 * 64];

// ---------------------------------------------------------------- helpers --
__device__ __forceinline__ unsigned smem_u32(const void* p) {
    return (unsigned)__cvta_generic_to_shared(p);
}
__device__ __forceinline__ void cp_async16(unsigned dst, const void* src) {
    asm volatile("cp.async.cg.shared.global [%0], [%1], 16;" :: "r"(dst), "l"(src));
}
__device__ __forceinline__ void ldsm4(unsigned &r0, unsigned &r1,
                                      unsigned &r2, unsigned &r3, unsigned a) {
    asm volatile("ldmatrix.sync.aligned.m8n8.x4.shared.b16 {%0,%1,%2,%3}, [%4];"
                 : "=r"(r0), "=r"(r1), "=r"(r2), "=r"(r3) : "r"(a));
}
__device__ __forceinline__ void mma_f16(float &c0, float &c1, float &c2, float &c3,
                                        unsigned a0, unsigned a1, unsigned a2,
                                        unsigned a3, unsigned b0, unsigned b1) {
    asm volatile(
        "mma.sync.aligned.m16n8k16.row.col.f32.f16.f16.f32 "
        "{%0,%1,%2,%3}, {%4,%5,%6,%7}, {%8,%9}, {%0,%1,%2,%3};"
        : "+f"(c0), "+f"(c1), "+f"(c2), "+f"(c3)
        : "r"(a0), "r"(a1), "r"(a2), "r"(a3), "r"(b0), "r"(b1));
}
__device__ __forceinline__ void split2(float v, float &h, float &l) {
    h = __half2float(__float2half_rn(v));
    l = v - h;
}
__device__ __forceinline__ unsigned packh(float a, float b) {
    __half2 t = __floats2half2_rn(a, b);
    return *(unsigned*)&t;
}

// smem layout (bytes), rows 80B-strided (32 fp16 + 16B pad):
//   A  : 2 splits x 64 x 80           = 10240
//   B  : 2 bufs x 2 splits x 128 x 80 = 40960
//   sB1 512  sW2 512  red 512  rnz 512  steal 16
#define A_OFF     0
#define B_OFF     10240
#define SB1_OFF   51200
#define SW2_OFF   51712
#define RED_OFF   52224
#define RNZ_OFF   52736
#define STEAL_OFF 53248
#define SMEM_BYTES 53264
#define A_SPLIT   5120
#define B_SPLIT   10240
#define BBUF_STRIDE 20480

// ---------------------------------------------------------------------------
// W prep: split W1[k=512][u=128] into h/l fp16, transposed [s][u][k]; also
// resets the work-stealing counter for this launch.
// ---------------------------------------------------------------------------
__global__ void wprep_kernel(const float* __restrict__ W1) {
    if (blockIdx.x == 0 && threadIdx.x == 0) g_tile = 0;
    int g = blockIdx.x * 256 + threadIdx.x;
    if (g >= 2 * 64 * 128) return;
    int s = g >> 13;
    int rem = g & 8191;
    int kg = rem >> 7;
    int n = rem & 127;
    unsigned w[4];
#pragma unroll
    for (int q = 0; q < 4; q++) {
        float sp[2][2];
#pragma unroll
        for (int t = 0; t < 2; t++) {
            float v = W1[(kg * 8 + q * 2 + t) * 128 + n];
            split2(v, sp[t][0], sp[t][1]);
        }
        w[q] = packh(sp[0][s], sp[1][s]);
    }
    uint4 u; u.x = w[0]; u.y = w[1]; u.z = w[2]; u.w = w[3];
    g_w[(s * 128 + n) * 64 + kg] = u;
}

// ---------------------------------------------------------------------------
// Kernel A: persistent 3-product fp16-split GEMM + relu/W2/mask epilogue,
// plus streaming zero-fill of d_out for each tile's 64 frames.
// Tile = 64 frames x 128 U; 256 threads (8 warps), warp tile 16x64, occ 2.
// ---------------------------------------------------------------------------
__global__ __launch_bounds__(256, 2) void score_kernel(
    const float* __restrict__ x, const float* __restrict__ b1,
    const float* __restrict__ W2, const float* __restrict__ b2,
    float* __restrict__ out)
{
    extern __shared__ char smc[];
    const unsigned smb = smem_u32(smc);
    float* sB1 = (float*)(smc + SB1_OFF);
    float* sW2 = (float*)(smc + SW2_OFF);
    float* red = (float*)(smc + RED_OFF);
    unsigned* rnz = (unsigned*)(smc + RNZ_OFF);
    int* sSteal = (int*)(smc + STEAL_OFF);

    const int tid = threadIdx.x;
    const int w = tid >> 5;
    const int l = tid & 31;

    if (tid < 128) { sB1[tid] = b1[tid]; sW2[tid] = W2[tid]; }

    const int arow = tid >> 2, akg = tid & 3;   // A staging: 64 rows x 4 kg
    const int mrow0 = (w & 3) * 16;
    const int nb0 = (w >> 2) * 64;
    const unsigned a_lm = smb + A_OFF + (mrow0 + (l & 15)) * 80 + (l >> 4) * 16;
    const unsigned b_lm_row = (l & 7) * 80 + (l >> 3) * 16;
    float4* o4 = (float4*)out;

    for (;;) {
        if (tid == 0) *sSteal = atomicAdd(&g_tile, 1);
        __syncthreads();                 // broadcast tile + prior-tile smem free
        const int tile = *sSteal;
        if (tile >= NTILES) break;
        const int bm0 = tile << 6;

        const float4* xg4 = (const float4*)x + (size_t)(bm0 + arow) * 128 + akg * 2;
        float4 xr0 = xg4[0], xr1 = xg4[1];

        auto load_B = [&](int c) {
            unsigned base = smb + B_OFF + (unsigned)((c & 1) * BBUF_STRIDE);
#pragma unroll
            for (int p = 0; p < 4; p++) {
                int e = tid + p * 256;
                int s = e >> 9, i = e & 511;
                int n = i >> 2, j = i & 3;
                cp_async16(base + s * B_SPLIT + n * 80 + j * 16,
                           &g_w[(s * 128 + n) * 64 + c * 4 + j]);
            }
            asm volatile("cp.async.commit_group;" ::: "memory");
        };
        load_B(0);

        float acc[8][4];
#pragma unroll
        for (int nt = 0; nt < 8; nt++)
#pragma unroll
            for (int q = 0; q < 4; q++) acc[nt][q] = 0.f;

        for (int c = 0; c < 16; c++) {
            __syncthreads();
            // convert x regs -> 2 fp16 A tiles (one STS.128 per split)
            {
                float v[8] = {xr0.x, xr0.y, xr0.z, xr0.w,
                              xr1.x, xr1.y, xr1.z, xr1.w};
                char* ab = smc + A_OFF + arow * 80 + akg * 16;
                uint4 hw, lw;
                unsigned* hp = (unsigned*)&hw;
                unsigned* lp = (unsigned*)&lw;
#pragma unroll
                for (int q = 0; q < 4; q++) {
                    float h0, l0, h1, l1;
                    split2(v[2 * q], h0, l0);
                    split2(v[2 * q + 1], h1, l1);
                    hp[q] = packh(h0, h1);
                    lp[q] = packh(l0, l1);
                }
                *(uint4*)(ab)           = hw;
                *(uint4*)(ab + A_SPLIT) = lw;
            }
            if (c + 1 < 16) {
                load_B(c + 1);
                xr0 = xg4[(c + 1) * 8];
                xr1 = xg4[(c + 1) * 8 + 1];
                asm volatile("cp.async.wait_group 1;" ::: "memory");
            } else {
                asm volatile("cp.async.wait_group 0;" ::: "memory");
            }
            __syncthreads();

            unsigned a[4][4];   // [split*2+ks][frag]
#pragma unroll
            for (int s = 0; s < 2; s++)
#pragma unroll
                for (int ks = 0; ks < 2; ks++)
                    ldsm4(a[s * 2 + ks][0], a[s * 2 + ks][1], a[s * 2 + ks][2],
                          a[s * 2 + ks][3], a_lm + s * A_SPLIT + ks * 32);

            const unsigned bbase = smb + B_OFF + (unsigned)((c & 1) * BBUF_STRIDE);
#pragma unroll
            for (int nt = 0; nt < 8; nt++) {
                unsigned b[2][4];
#pragma unroll
                for (int s = 0; s < 2; s++)
                    ldsm4(b[s][0], b[s][1], b[s][2], b[s][3],
                          bbase + s * B_SPLIT + (nb0 + nt * 8) * 80 + b_lm_row);
                float* cA = acc[nt];
#pragma unroll
                for (int ks = 0; ks < 2; ks++) {
                    unsigned* ah = a[0 * 2 + ks];
                    unsigned* al = a[1 * 2 + ks];
                    unsigned bh0 = b[0][ks * 2], bh1 = b[0][ks * 2 + 1];
                    unsigned bl0 = b[1][ks * 2], bl1 = b[1][ks * 2 + 1];
                    mma_f16(cA[0], cA[1], cA[2], cA[3], ah[0], ah[1], ah[2], ah[3], bh0, bh1);
                    mma_f16(cA[0], cA[1], cA[2], cA[3], ah[0], ah[1], ah[2], ah[3], bl0, bl1);
                    mma_f16(cA[0], cA[1], cA[2], cA[3], al[0], al[1], al[2], al[3], bh0, bh1);
                }
            }
        }

        // --- epilogue: relu + W2 dot + nz mask ---
        float p0 = 0.f, p1 = 0.f;
        unsigned nz0 = 0, nz1 = 0;
#pragma unroll
        for (int nt = 0; nt < 8; nt++) {
            int u0 = nb0 + nt * 8 + 2 * (l & 3);
            float ba = sB1[u0], bb = sB1[u0 + 1];
            float wa = sW2[u0], wb = sW2[u0 + 1];
            nz0 |= __float_as_uint(acc[nt][0]) | __float_as_uint(acc[nt][1]);
            nz1 |= __float_as_uint(acc[nt][2]) | __float_as_uint(acc[nt][3]);
            p0 += fmaxf(acc[nt][0] + ba, 0.f) * wa + fmaxf(acc[nt][1] + bb, 0.f) * wb;
            p1 += fmaxf(acc[nt][2] + ba, 0.f) * wa + fmaxf(acc[nt][3] + bb, 0.f) * wb;
        }
#pragma unroll
        for (int d = 1; d <= 2; d <<= 1) {
            p0 += __shfl_xor_sync(0xFFFFFFFFu, p0, d);
            p1 += __shfl_xor_sync(0xFFFFFFFFu, p1, d);
            nz0 |= __shfl_xor_sync(0xFFFFFFFFu, nz0, d);
            nz1 |= __shfl_xor_sync(0xFFFFFFFFu, nz1, d);
        }
        __syncthreads();
        if ((l & 3) == 0) {
            int half = w >> 2;
            int r0 = mrow0 + (l >> 2), r1 = r0 + 8;
            red[r0 * 2 + half] = p0;  red[r1 * 2 + half] = p1;
            rnz[r0 * 2 + half] = nz0; rnz[r1 * 2 + half] = nz1;
        }
        __syncthreads();
        if (tid < 64) {
            float s = red[tid * 2] + red[tid * 2 + 1] + b2[0];
            unsigned nz = rnz[tid * 2] | rnz[tid * 2 + 1];
            g_scores[bm0 + tid] = nz ? s : NEG_BIG;
        }

        // --- streaming zero-fill of this tile's output frames ---
        {
            float4 z = make_float4(0.f, 0.f, 0.f, 0.f);
            float4* ob = o4 + (size_t)bm0 * 128;
#pragma unroll
            for (int i = 0; i < 32; i++) __stcs(&ob[tid + i * 256], z);
        }
    }
}

// ---------------------------------------------------------------------------
// Kernel B: exact top-k per batch row via bitonic sort of (score, ~index);
// emits compact selected-frame list g_sel[row*kk + rank].
// ---------------------------------------------------------------------------
__global__ void topk_kernel(const int* kptr) {
    __shared__ unsigned long long sk[2048];
    const int row = blockIdx.x;
    const int tid = threadIdx.x;
    const float* sc = g_scores + row * 2048;

#pragma unroll
    for (int s = 0; s < 2; s++) {
        int t = tid + s * 1024;
        unsigned int u = __float_as_uint(sc[t]);
        u = (u & 0x80000000u) ? ~u : (u | 0x80000000u);
        sk[t] = ((unsigned long long)u << 32) | (unsigned long long)(~(unsigned int)t);
    }
    __syncthreads();

    for (int k = 2; k <= 2048; k <<= 1) {
        for (int j = k >> 1; j > 0; j >>= 1) {
#pragma unroll
            for (int s = 0; s < 2; s++) {
                int i = tid + s * 1024;
                int l = i ^ j;
                if (l > i) {
                    unsigned long long a = sk[i], b = sk[l];
                    bool up = ((i & k) == 0);
                    if ((a > b) == up) { sk[i] = b; sk[l] = a; }
                }
            }
            __syncthreads();
        }
    }

    int kk = (kptr != nullptr) ? kptr[0] : 64;
    if (kk < 1) kk = 1;
    if (kk > 2048) kk = 2048;
#pragma unroll
    for (int s = 0; s < 2; s++) {
        int i = tid + s * 1024;
        if (i >= 2048 - kk) {
            unsigned int t = ~(unsigned int)(sk[i] & 0xFFFFFFFFull);
            g_sel[row * kk + (i - (2048 - kk))] = row * 2048 + (int)t;
        }
    }
}

// ---------------------------------------------------------------------------
// Kernel C: gather — copy only selected frames (out already zero-filled).
// ---------------------------------------------------------------------------
__global__ void gather_kernel(const float* __restrict__ x,
                              float* __restrict__ out, const int* kptr) {
    int kk = (kptr != nullptr) ? kptr[0] : 64;
    if (kk < 1) kk = 1;
    if (kk > 2048) kk = 2048;
    const int total = 32 * kk;
    const float4* x4 = (const float4*)x;
    float4* o4 = (float4*)out;
    for (int slot = blockIdx.x; slot < total; slot += gridDim.x) {
        int fr = g_sel[slot];
        o4[(size_t)fr * 128 + threadIdx.x] = x4[(size_t)fr * 128 + threadIdx.x];
    }
}

extern "C" void kernel_launch(void* const* d_in, const int* in_sizes, int n_in,
                              void* d_out, int out_size) {
    const float* x  = (const float*)d_in[0];
    const float* W1 = (const float*)d_in[1];
    const float* b1 = (const float*)d_in[2];
    const float* W2 = (const float*)d_in[3];
    const float* b2 = (const float*)d_in[4];
    const int* kptr = (n_in >= 6) ? (const int*)d_in[5] : nullptr;

    cudaFuncSetAttribute(score_kernel,
                         cudaFuncAttributeMaxDynamicSharedMemorySize,
                         SMEM_BYTES);
    wprep_kernel<<<64, 256>>>(W1);
    score_kernel<<<296, 256, SMEM_BYTES>>>(x, b1, W2, b2, (float*)d_out);
    topk_kernel<<<32, 1024>>>(kptr);
    gather_kernel<<<2048, 128>>>(x, (float*)d_out, kptr);
}

// round 15
// speedup vs baseline: 1.9629x; 1.0967x over previous
#include <cuda_runtime.h>
#include <cuda_fp16.h>

// RLFrameSelector via warp-level fp16 mma.sync. scores = relu(x@W1+b1)@W2+b2
// with a 3-product 2-way fp16 split (h+l, 22 mantissa bits), mask, exact
// top-k, gather. B=32,T=2048,F=512,U=128.
// R12: topk switched from full bitonic sort (66 barrier phases) to exact
// histogram-select (11-bit bins + suffix scan + tiny tie-break sort).

#define NEG_BIG -1.0e9f
#define NTILES 1024

__device__ float g_scores[65536];
__device__ int g_sel[65536];
__device__ int g_tile;
// W1 split h/l, transposed to [split][u=128][k=512] fp16 packed as uint4
// (8 k-values). uint4 index = (s*128 + n)*64 + kg, kg = k/8.
__device__ uint4 g_w[2 * 128 * 64];

// ---------------------------------------------------------------- helpers --
__device__ __forceinline__ unsigned smem_u32(const void* p) {
    return (unsigned)__cvta_generic_to_shared(p);
}
__device__ __forceinline__ void cp_async16(unsigned dst, const void* src) {
    asm volatile("cp.async.cg.shared.global [%0], [%1], 16;" :: "r"(dst), "l"(src));
}
__device__ __forceinline__ void ldsm4(unsigned &r0, unsigned &r1,
                                      unsigned &r2, unsigned &r3, unsigned a) {
    asm volatile("ldmatrix.sync.aligned.m8n8.x4.shared.b16 {%0,%1,%2,%3}, [%4];"
                 : "=r"(r0), "=r"(r1), "=r"(r2), "=r"(r3) : "r"(a));
}
__device__ __forceinline__ void mma_f16(float &c0, float &c1, float &c2, float &c3,
                                        unsigned a0, unsigned a1, unsigned a2,
                                        unsigned a3, unsigned b0, unsigned b1) {
    asm volatile(
        "mma.sync.aligned.m16n8k16.row.col.f32.f16.f16.f32 "
        "{%0,%1,%2,%3}, {%4,%5,%6,%7}, {%8,%9}, {%0,%1,%2,%3};"
        : "+f"(c0), "+f"(c1), "+f"(c2), "+f"(c3)
        : "r"(a0), "r"(a1), "r"(a2), "r"(a3), "r"(b0), "r"(b1));
}
__device__ __forceinline__ void split2(float v, float &h, float &l) {
    h = __half2float(__float2half_rn(v));
    l = v - h;
}
__device__ __forceinline__ unsigned packh(float a, float b) {
    __half2 t = __floats2half2_rn(a, b);
    return *(unsigned*)&t;
}

// smem layout (bytes), rows 80B-strided (32 fp16 + 16B pad):
//   A  : 2 splits x 64 x 80           = 10240
//   B  : 2 bufs x 2 splits x 128 x 80 = 40960
//   sB1 512  sW2 512  red 512  rnz 512  steal 16
#define A_OFF     0
#define B_OFF     10240
#define SB1_OFF   51200
#define SW2_OFF   51712
#define RED_OFF   52224
#define RNZ_OFF   52736
#define STEAL_OFF 53248
#define SMEM_BYTES 53264
#define A_SPLIT   5120
#define B_SPLIT   10240
#define BBUF_STRIDE 20480

// ---------------------------------------------------------------------------
// W prep: split W1[k=512][u=128] into h/l fp16, transposed [s][u][k]; also
// resets the work-stealing counter for this launch.
// ---------------------------------------------------------------------------
__global__ void wprep_kernel(const float* __restrict__ W1) {
    if (blockIdx.x == 0 && threadIdx.x == 0) g_tile = 0;
    int g = blockIdx.x * 256 + threadIdx.x;
    if (g >= 2 * 64 * 128) return;
    int s = g >> 13;
    int rem = g & 8191;
    int kg = rem >> 7;
    int n = rem & 127;
    unsigned w[4];
#pragma unroll
    for (int q = 0; q < 4; q++) {
        float sp[2][2];
#pragma unroll
        for (int t = 0; t < 2; t++) {
            float v = W1[(kg * 8 + q * 2 + t) * 128 + n];
            split2(v, sp[t][0], sp[t][1]);
        }
        w[q] = packh(sp[0][s], sp[1][s]);
    }
    uint4 u; u.x = w[0]; u.y = w[1]; u.z = w[2]; u.w = w[3];
    g_w[(s * 128 + n) * 64 + kg] = u;
}

// ---------------------------------------------------------------------------
// Kernel A: persistent 3-product fp16-split GEMM + relu/W2/mask epilogue,
// plus streaming zero-fill of d_out for each tile's 64 frames.
// Tile = 64 frames x 128 U; 256 threads (8 warps), warp tile 16x64, occ 2.
// ---------------------------------------------------------------------------
__global__ __launch_bounds__(256, 2) void score_kernel(
    const float* __restrict__ x, const float* __restrict__ b1,
    const float* __restrict__ W2, const float* __restrict__ b2,
    float* __restrict__ out)
{
    extern __shared__ char smc[];
    const unsigned smb = smem_u32(smc);
    float* sB1 = (float*)(smc + SB1_OFF);
    float* sW2 = (float*)(smc + SW2_OFF);
    float* red = (float*)(smc + RED_OFF);
    unsigned* rnz = (unsigned*)(smc + RNZ_OFF);
    int* sSteal = (int*)(smc + STEAL_OFF);

    const int tid = threadIdx.x;
    const int w = tid >> 5;
    const int l = tid & 31;

    if (tid < 128) { sB1[tid] = b1[tid]; sW2[tid] = W2[tid]; }

    const int arow = tid >> 2, akg = tid & 3;   // A staging: 64 rows x 4 kg
    const int mrow0 = (w & 3) * 16;
    const int nb0 = (w >> 2) * 64;
    const unsigned a_lm = smb + A_OFF + (mrow0 + (l & 15)) * 80 + (l >> 4) * 16;
    const unsigned b_lm_row = (l & 7) * 80 + (l >> 3) * 16;
    float4* o4 = (float4*)out;

    for (;;) {
        if (tid == 0) *sSteal = atomicAdd(&g_tile, 1);
        __syncthreads();                 // broadcast tile + prior-tile smem free
        const int tile = *sSteal;
        if (tile >= NTILES) break;
        const int bm0 = tile << 6;

        const float4* xg4 = (const float4*)x + (size_t)(bm0 + arow) * 128 + akg * 2;
        float4 xr0 = xg4[0], xr1 = xg4[1];

        auto load_B = [&](int c) {
            unsigned base = smb + B_OFF + (unsigned)((c & 1) * BBUF_STRIDE);
#pragma unroll
            for (int p = 0; p < 4; p++) {
                int e = tid + p * 256;
                int s = e >> 9, i = e & 511;
                int n = i >> 2, j = i & 3;
                cp_async16(base + s * B_SPLIT + n * 80 + j * 16,
                           &g_w[(s * 128 + n) * 64 + c * 4 + j]);
            }
            asm volatile("cp.async.commit_group;" ::: "memory");
        };
        load_B(0);

        float acc[8][4];
#pragma unroll
        for (int nt = 0; nt < 8; nt++)
#pragma unroll
            for (int q = 0; q < 4; q++) acc[nt][q] = 0.f;

        for (int c = 0; c < 16; c++) {
            __syncthreads();
            // convert x regs -> 2 fp16 A tiles (one STS.128 per split)
            {
                float v[8] = {xr0.x, xr0.y, xr0.z, xr0.w,
                              xr1.x, xr1.y, xr1.z, xr1.w};
                char* ab = smc + A_OFF + arow * 80 + akg * 16;
                uint4 hw, lw;
                unsigned* hp = (unsigned*)&hw;
                unsigned* lp = (unsigned*)&lw;
#pragma unroll
                for (int q = 0; q < 4; q++) {
                    float h0, l0, h1, l1;
                    split2(v[2 * q], h0, l0);
                    split2(v[2 * q + 1], h1, l1);
                    hp[q] = packh(h0, h1);
                    lp[q] = packh(l0, l1);
                }
                *(uint4*)(ab)           = hw;
                *(uint4*)(ab + A_SPLIT) = lw;
            }
            if (c + 1 < 16) {
                load_B(c + 1);
                xr0 = xg4[(c + 1) * 8];
                xr1 = xg4[(c + 1) * 8 + 1];
                asm volatile("cp.async.wait_group 1;" ::: "memory");
            } else {
                asm volatile("cp.async.wait_group 0;" ::: "memory");
            }
            __syncthreads();

            unsigned a[4][4];   // [split*2+ks][frag]
#pragma unroll
            for (int s = 0; s < 2; s++)
#pragma unroll
                for (int ks = 0; ks < 2; ks++)
                    ldsm4(a[s * 2 + ks][0], a[s * 2 + ks][1], a[s * 2 + ks][2],
                          a[s * 2 + ks][3], a_lm + s * A_SPLIT + ks * 32);

            const unsigned bbase = smb + B_OFF + (unsigned)((c & 1) * BBUF_STRIDE);
#pragma unroll
            for (int nt = 0; nt < 8; nt++) {
                unsigned b[2][4];
#pragma unroll
                for (int s = 0; s < 2; s++)
                    ldsm4(b[s][0], b[s][1], b[s][2], b[s][3],
                          bbase + s * B_SPLIT + (nb0 + nt * 8) * 80 + b_lm_row);
                float* cA = acc[nt];
#pragma unroll
                for (int ks = 0; ks < 2; ks++) {
                    unsigned* ah = a[0 * 2 + ks];
                    unsigned* al = a[1 * 2 + ks];
                    unsigned bh0 = b[0][ks * 2], bh1 = b[0][ks * 2 + 1];
                    unsigned bl0 = b[1][ks * 2], bl1 = b[1][ks * 2 + 1];
                    mma_f16(cA[0], cA[1], cA[2], cA[3], ah[0], ah[1], ah[2], ah[3], bh0, bh1);
                    mma_f16(cA[0], cA[1], cA[2], cA[3], ah[0], ah[1], ah[2], ah[3], bl0, bl1);
                    mma_f16(cA[0], cA[1], cA[2], cA[3], al[0], al[1], al[2], al[3], bh0, bh1);
                }
            }
        }

        // --- epilogue: relu + W2 dot + nz mask ---
        float p0 = 0.f, p1 = 0.f;
        unsigned nz0 = 0, nz1 = 0;
#pragma unroll
        for (int nt = 0; nt < 8; nt++) {
            int u0 = nb0 + nt * 8 + 2 * (l & 3);
            float ba = sB1[u0], bb = sB1[u0 + 1];
            float wa = sW2[u0], wb = sW2[u0 + 1];
            nz0 |= __float_as_uint(acc[nt][0]) | __float_as_uint(acc[nt][1]);
            nz1 |= __float_as_uint(acc[nt][2]) | __float_as_uint(acc[nt][3]);
            p0 += fmaxf(acc[nt][0] + ba, 0.f) * wa + fmaxf(acc[nt][1] + bb, 0.f) * wb;
            p1 += fmaxf(acc[nt][2] + ba, 0.f) * wa + fmaxf(acc[nt][3] + bb, 0.f) * wb;
        }
#pragma unroll
        for (int d = 1; d <= 2; d <<= 1) {
            p0 += __shfl_xor_sync(0xFFFFFFFFu, p0, d);
            p1 += __shfl_xor_sync(0xFFFFFFFFu, p1, d);
            nz0 |= __shfl_xor_sync(0xFFFFFFFFu, nz0, d);
            nz1 |= __shfl_xor_sync(0xFFFFFFFFu, nz1, d);
        }
        __syncthreads();
        if ((l & 3) == 0) {
            int half = w >> 2;
            int r0 = mrow0 + (l >> 2), r1 = r0 + 8;
            red[r0 * 2 + half] = p0;  red[r1 * 2 + half] = p1;
            rnz[r0 * 2 + half] = nz0; rnz[r1 * 2 + half] = nz1;
        }
        __syncthreads();
        if (tid < 64) {
            float s = red[tid * 2] + red[tid * 2 + 1] + b2[0];
            unsigned nz = rnz[tid * 2] | rnz[tid * 2 + 1];
            g_scores[bm0 + tid] = nz ? s : NEG_BIG;
        }

        // --- streaming zero-fill of this tile's output frames ---
        {
            float4 z = make_float4(0.f, 0.f, 0.f, 0.f);
            float4* ob = o4 + (size_t)bm0 * 128;
#pragma unroll
            for (int i = 0; i < 32; i++) __stcs(&ob[tid + i * 256], z);
        }
    }
}

// ---------------------------------------------------------------------------
// Kernel B: exact top-k per row via histogram select.
// Monotone-map scores to unsigned; 2048-bin histogram on top 11 bits;
// suffix scan finds threshold bin b* and k'. Elements above b* are selected
// outright; ties within b* broken by (remaining 21 score bits, smaller
// index) via a small bitonic sort of just the candidates. Selection-set
// membership fully determines the output, so g_sel slot order is free.
// ---------------------------------------------------------------------------
__global__ void topk_kernel(const int* kptr) {
    __shared__ int hist[2048];
    __shared__ int sufb[2048];
    __shared__ unsigned long long cand[2048];
    __shared__ int sc4[4];   // [0]=nsel [1]=ncand [2]=bstar [3]=kprime

    const int row = blockIdx.x;
    const int tid = threadIdx.x;
    const float* sc = g_scores + row * 2048;

    int kk = (kptr != nullptr) ? kptr[0] : 64;
    if (kk < 1) kk = 1;
    if (kk > 2048) kk = 2048;

    hist[tid] = 0; hist[tid + 1024] = 0;
    if (tid < 4) sc4[tid] = 0;
    __syncthreads();

    unsigned key[2];
#pragma unroll
    for (int s = 0; s < 2; s++) {
        int t = tid + s * 1024;
        unsigned u = __float_as_uint(sc[t]);
        key[s] = (u & 0x80000000u) ? ~u : (u | 0x80000000u);
        atomicAdd(&hist[key[s] >> 21], 1);
    }
    __syncthreads();

    // inclusive suffix scan over 2048 bins (ping-pong Hillis-Steele)
    int* cur = hist;
    int* nxt = sufb;
    for (int s = 1; s < 2048; s <<= 1) {
#pragma unroll
        for (int q = 0; q < 2; q++) {
            int b = tid + q * 1024;
            nxt[b] = cur[b] + ((b + s < 2048) ? cur[b + s] : 0);
        }
        __syncthreads();
        int* tmp = cur; cur = nxt; nxt = tmp;
    }

    // find threshold bin: suf[b] >= kk and (b==2047 or suf[b+1] < kk)
#pragma unroll
    for (int q = 0; q < 2; q++) {
        int b = tid + q * 1024;
        int above = (b == 2047) ? 0 : cur[b + 1];
        if (cur[b] >= kk && above < kk) {
            sc4[2] = b;
            sc4[3] = kk - above;
        }
    }
    __syncthreads();
    const int bstar = sc4[2];
    const int kprime = sc4[3];

    // pass 2: emit definite selections; collect threshold-bin candidates
#pragma unroll
    for (int s = 0; s < 2; s++) {
        int t = tid + s * 1024;
        int b = key[s] >> 21;
        if (b > bstar) {
            int pos = atomicAdd(&sc4[0], 1);
            g_sel[row * kk + pos] = row * 2048 + t;
        } else if (b == bstar) {
            int c = atomicAdd(&sc4[1], 1);
            // 64-bit tie-break key: (low 21 score bits, then smaller index),
            // bit0=1 marks real entries (pad = 0 sorts below all).
            cand[c] = (((unsigned long long)(key[s] & 0x1FFFFFu)) << 13)
                    | ((unsigned long long)(2047 - t) << 2) | 1ull;
        }
    }
    __syncthreads();

    const int ncand = sc4[1];
    const int nsel = sc4[0];           // == kk - kprime
    int C2 = 1;
    while (C2 < ncand) C2 <<= 1;

    // pad and bitonic-sort C2 candidates ascending
#pragma unroll
    for (int s = 0; s < 2; s++) {
        int i = tid + s * 1024;
        if (i >= ncand && i < C2) cand[i] = 0ull;
    }
    __syncthreads();
    for (int k = 2; k <= C2; k <<= 1) {
        for (int j = k >> 1; j > 0; j >>= 1) {
#pragma unroll
            for (int s = 0; s < 2; s++) {
                int i = tid + s * 1024;
                int l = i ^ j;
                if (i < C2 && l > i) {
                    unsigned long long a = cand[i], b = cand[l];
                    bool up = ((i & k) == 0);
                    if ((a > b) == up) { cand[i] = b; cand[l] = a; }
                }
            }
            __syncthreads();
        }
    }

    // top k' of the candidates complete the selection
#pragma unroll
    for (int s = 0; s < 2; s++) {
        int i = tid + s * 1024;
        if (i >= C2 - kprime && i < C2) {
            int t = 2047 - (int)((cand[i] >> 2) & 2047ull);
            g_sel[row * kk + nsel + (i - (C2 - kprime))] = row * 2048 + t;
        }
    }
}

// ---------------------------------------------------------------------------
// Kernel C: gather — copy only selected frames (out already zero-filled).
// ---------------------------------------------------------------------------
__global__ void gather_kernel(const float* __restrict__ x,
                              float* __restrict__ out, const int* kptr) {
    int kk = (kptr != nullptr) ? kptr[0] : 64;
    if (kk < 1) kk = 1;
    if (kk > 2048) kk = 2048;
    const int total = 32 * kk;
    const float4* x4 = (const float4*)x;
    float4* o4 = (float4*)out;
    for (int slot = blockIdx.x; slot < total; slot += gridDim.x) {
        int fr = g_sel[slot];
        o4[(size_t)fr * 128 + threadIdx.x] = x4[(size_t)fr * 128 + threadIdx.x];
    }
}

extern "C" void kernel_launch(void* const* d_in, const int* in_sizes, int n_in,
                              void* d_out, int out_size) {
    const float* x  = (const float*)d_in[0];
    const float* W1 = (const float*)d_in[1];
    const float* b1 = (const float*)d_in[2];
    const float* W2 = (const float*)d_in[3];
    const float* b2 = (const float*)d_in[4];
    const int* kptr = (n_in >= 6) ? (const int*)d_in[5] : nullptr;

    cudaFuncSetAttribute(score_kernel,
                         cudaFuncAttributeMaxDynamicSharedMemorySize,
                         SMEM_BYTES);
    wprep_kernel<<<64, 256>>>(W1);
    score_kernel<<<296, 256, SMEM_BYTES>>>(x, b1, W2, b2, (float*)d_out);
    topk_kernel<<<32, 1024>>>(kptr);
    gather_kernel<<<2048, 128>>>(x, (float*)d_out, kptr);
}

// round 17
// speedup vs baseline: 2.0390x; 1.0388x over previous
#include <cuda_runtime.h>
#include <cuda_fp16.h>

// RLFrameSelector via warp-level fp16 mma.sync. scores = relu(x@W1+b1)@W2+b2
// with a 3-product 2-way fp16 split (h+l, 22 mantissa bits), mask, exact
// top-k, gather. B=32,T=2048,F=512,U=128.
// R16: score kernel at occupancy 3 (grid 444, launch_bounds(256,3)); inner
// loop restructured ks-outer with ldmatrix.x2 B loads to fit 84 regs.
// Per-accumulator FP order unchanged -> scores bit-identical to R12.

#define NEG_BIG -1.0e9f
#define NTILES 1024

__device__ float g_scores[65536];
__device__ int g_sel[65536];
__device__ int g_tile;
// W1 split h/l, transposed to [split][u=128][k=512] fp16 packed as uint4
// (8 k-values). uint4 index = (s*128 + n)*64 + kg, kg = k/8.
__device__ uint4 g_w[2 * 128 * 64];

// ---------------------------------------------------------------- helpers --
__device__ __forceinline__ unsigned smem_u32(const void* p) {
    return (unsigned)__cvta_generic_to_shared(p);
}
__device__ __forceinline__ void cp_async16(unsigned dst, const void* src) {
    asm volatile("cp.async.cg.shared.global [%0], [%1], 16;" :: "r"(dst), "l"(src));
}
__device__ __forceinline__ void ldsm4(unsigned &r0, unsigned &r1,
                                      unsigned &r2, unsigned &r3, unsigned a) {
    asm volatile("ldmatrix.sync.aligned.m8n8.x4.shared.b16 {%0,%1,%2,%3}, [%4];"
                 : "=r"(r0), "=r"(r1), "=r"(r2), "=r"(r3) : "r"(a));
}
__device__ __forceinline__ void ldsm2(unsigned &r0, unsigned &r1, unsigned a) {
    asm volatile("ldmatrix.sync.aligned.m8n8.x2.shared.b16 {%0,%1}, [%2];"
                 : "=r"(r0), "=r"(r1) : "r"(a));
}
__device__ __forceinline__ void mma_f16(float &c0, float &c1, float &c2, float &c3,
                                        unsigned a0, unsigned a1, unsigned a2,
                                        unsigned a3, unsigned b0, unsigned b1) {
    asm volatile(
        "mma.sync.aligned.m16n8k16.row.col.f32.f16.f16.f32 "
        "{%0,%1,%2,%3}, {%4,%5,%6,%7}, {%8,%9}, {%0,%1,%2,%3};"
        : "+f"(c0), "+f"(c1), "+f"(c2), "+f"(c3)
        : "r"(a0), "r"(a1), "r"(a2), "r"(a3), "r"(b0), "r"(b1));
}
__device__ __forceinline__ void split2(float v, float &h, float &l) {
    h = __half2float(__float2half_rn(v));
    l = v - h;
}
__device__ __forceinline__ unsigned packh(float a, float b) {
    __half2 t = __floats2half2_rn(a, b);
    return *(unsigned*)&t;
}

// smem layout (bytes), rows 80B-strided (32 fp16 + 16B pad):
//   A  : 2 splits x 64 x 80           = 10240
//   B  : 2 bufs x 2 splits x 128 x 80 = 40960
//   sB1 512  sW2 512  red 512  rnz 512  steal 16
#define A_OFF     0
#define B_OFF     10240
#define SB1_OFF   51200
#define SW2_OFF   51712
#define RED_OFF   52224
#define RNZ_OFF   52736
#define STEAL_OFF 53248
#define SMEM_BYTES 53264
#define A_SPLIT   5120
#define B_SPLIT   10240
#define BBUF_STRIDE 20480

// ---------------------------------------------------------------------------
// W prep: split W1[k=512][u=128] into h/l fp16, transposed [s][u][k]; also
// resets the work-stealing counter for this launch.
// ---------------------------------------------------------------------------
__global__ void wprep_kernel(const float* __restrict__ W1) {
    if (blockIdx.x == 0 && threadIdx.x == 0) g_tile = 0;
    int g = blockIdx.x * 256 + threadIdx.x;
    if (g >= 2 * 64 * 128) return;
    int s = g >> 13;
    int rem = g & 8191;
    int kg = rem >> 7;
    int n = rem & 127;
    unsigned w[4];
#pragma unroll
    for (int q = 0; q < 4; q++) {
        float sp[2][2];
#pragma unroll
        for (int t = 0; t < 2; t++) {
            float v = W1[(kg * 8 + q * 2 + t) * 128 + n];
            split2(v, sp[t][0], sp[t][1]);
        }
        w[q] = packh(sp[0][s], sp[1][s]);
    }
    uint4 u; u.x = w[0]; u.y = w[1]; u.z = w[2]; u.w = w[3];
    g_w[(s * 128 + n) * 64 + kg] = u;
}

// ---------------------------------------------------------------------------
// Kernel A: persistent 3-product fp16-split GEMM + relu/W2/mask epilogue,
// plus streaming zero-fill of d_out for each tile's 64 frames.
// Tile = 64 frames x 128 U; 256 threads (8 warps), warp tile 16x64, occ 3.
// ---------------------------------------------------------------------------
__global__ __launch_bounds__(256, 3) void score_kernel(
    const float* __restrict__ x, const float* __restrict__ b1,
    const float* __restrict__ W2, const float* __restrict__ b2,
    float* __restrict__ out)
{
    extern __shared__ char smc[];
    const unsigned smb = smem_u32(smc);
    float* sB1 = (float*)(smc + SB1_OFF);
    float* sW2 = (float*)(smc + SW2_OFF);
    float* red = (float*)(smc + RED_OFF);
    unsigned* rnz = (unsigned*)(smc + RNZ_OFF);
    int* sSteal = (int*)(smc + STEAL_OFF);

    const int tid = threadIdx.x;
    const int w = tid >> 5;
    const int l = tid & 31;

    if (tid < 128) { sB1[tid] = b1[tid]; sW2[tid] = W2[tid]; }

    const int arow = tid >> 2, akg = tid & 3;   // A staging: 64 rows x 4 kg
    const int mrow0 = (w & 3) * 16;
    const int nb0 = (w >> 2) * 64;
    const unsigned a_lm = smb + A_OFF + (mrow0 + (l & 15)) * 80 + (l >> 4) * 16;
    // x2 ldmatrix row addr (lanes 0-15 consumed): row (l&7), matrix (l>>3)&1
    const unsigned b_lm2 = ((l & 7) * 80) + (((l >> 3) & 1) * 16);
    float4* o4 = (float4*)out;

    for (;;) {
        if (tid == 0) *sSteal = atomicAdd(&g_tile, 1);
        __syncthreads();                 // broadcast tile + prior-tile smem free
        const int tile = *sSteal;
        if (tile >= NTILES) break;
        const int bm0 = tile << 6;

        const float4* xg4 = (const float4*)x + (size_t)(bm0 + arow) * 128 + akg * 2;
        float4 xr0 = xg4[0], xr1 = xg4[1];

        auto load_B = [&](int c) {
            unsigned base = smb + B_OFF + (unsigned)((c & 1) * BBUF_STRIDE);
#pragma unroll
            for (int p = 0; p < 4; p++) {
                int e = tid + p * 256;
                int s = e >> 9, i = e & 511;
                int n = i >> 2, j = i & 3;
                cp_async16(base + s * B_SPLIT + n * 80 + j * 16,
                           &g_w[(s * 128 + n) * 64 + c * 4 + j]);
            }
            asm volatile("cp.async.commit_group;" ::: "memory");
        };
        load_B(0);

        float acc[8][4];
#pragma unroll
        for (int nt = 0; nt < 8; nt++)
#pragma unroll
            for (int q = 0; q < 4; q++) acc[nt][q] = 0.f;

        for (int c = 0; c < 16; c++) {
            __syncthreads();
            // convert x regs -> 2 fp16 A tiles (one STS.128 per split)
            {
                float v[8] = {xr0.x, xr0.y, xr0.z, xr0.w,
                              xr1.x, xr1.y, xr1.z, xr1.w};
                char* ab = smc + A_OFF + arow * 80 + akg * 16;
                uint4 hw, lw;
                unsigned* hp = (unsigned*)&hw;
                unsigned* lp = (unsigned*)&lw;
#pragma unroll
                for (int q = 0; q < 4; q++) {
                    float h0, l0, h1, l1;
                    split2(v[2 * q], h0, l0);
                    split2(v[2 * q + 1], h1, l1);
                    hp[q] = packh(h0, h1);
                    lp[q] = packh(l0, l1);
                }
                *(uint4*)(ab)           = hw;
                *(uint4*)(ab + A_SPLIT) = lw;
            }
            if (c + 1 < 16) {
                load_B(c + 1);
                xr0 = xg4[(c + 1) * 8];
                xr1 = xg4[(c + 1) * 8 + 1];
                asm volatile("cp.async.wait_group 1;" ::: "memory");
            } else {
                asm volatile("cp.async.wait_group 0;" ::: "memory");
            }
            __syncthreads();

            // --- compute chunk c: ks-outer, low register pressure ---
            const unsigned bbase = smb + B_OFF + (unsigned)((c & 1) * BBUF_STRIDE);
#pragma unroll
            for (int ks = 0; ks < 2; ks++) {
                unsigned ah[4], al[4];
                ldsm4(ah[0], ah[1], ah[2], ah[3], a_lm + ks * 32);
                ldsm4(al[0], al[1], al[2], al[3], a_lm + A_SPLIT + ks * 32);
#pragma unroll
                for (int nt = 0; nt < 8; nt++) {
                    unsigned bh0, bh1, bl0, bl1;
                    unsigned brow = (nb0 + nt * 8) * 80 + b_lm2 + ks * 32;
                    ldsm2(bh0, bh1, bbase + brow);
                    ldsm2(bl0, bl1, bbase + B_SPLIT + brow);
                    float* cA = acc[nt];
                    mma_f16(cA[0], cA[1], cA[2], cA[3],
                            ah[0], ah[1], ah[2], ah[3], bh0, bh1);  // hh
                    mma_f16(cA[0], cA[1], cA[2], cA[3],
                            ah[0], ah[1], ah[2], ah[3], bl0, bl1);  // hl
                    mma_f16(cA[0], cA[1], cA[2], cA[3],
                            al[0], al[1], al[2], al[3], bh0, bh1);  // lh
                }
            }
        }

        // --- epilogue: relu + W2 dot + nz mask ---
        float p0 = 0.f, p1 = 0.f;
        unsigned nz0 = 0, nz1 = 0;
#pragma unroll
        for (int nt = 0; nt < 8; nt++) {
            int u0 = nb0 + nt * 8 + 2 * (l & 3);
            float ba = sB1[u0], bb = sB1[u0 + 1];
            float wa = sW2[u0], wb = sW2[u0 + 1];
            nz0 |= __float_as_uint(acc[nt][0]) | __float_as_uint(acc[nt][1]);
            nz1 |= __float_as_uint(acc[nt][2]) | __float_as_uint(acc[nt][3]);
            p0 += fmaxf(acc[nt][0] + ba, 0.f) * wa + fmaxf(acc[nt][1] + bb, 0.f) * wb;
            p1 += fmaxf(acc[nt][2] + ba, 0.f) * wa + fmaxf(acc[nt][3] + bb, 0.f) * wb;
        }
#pragma unroll
        for (int d = 1; d <= 2; d <<= 1) {
            p0 += __shfl_xor_sync(0xFFFFFFFFu, p0, d);
            p1 += __shfl_xor_sync(0xFFFFFFFFu, p1, d);
            nz0 |= __shfl_xor_sync(0xFFFFFFFFu, nz0, d);
            nz1 |= __shfl_xor_sync(0xFFFFFFFFu, nz1, d);
        }
        __syncthreads();
        if ((l & 3) == 0) {
            int half = w >> 2;
            int r0 = mrow0 + (l >> 2), r1 = r0 + 8;
            red[r0 * 2 + half] = p0;  red[r1 * 2 + half] = p1;
            rnz[r0 * 2 + half] = nz0; rnz[r1 * 2 + half] = nz1;
        }
        __syncthreads();
        if (tid < 64) {
            float s = red[tid * 2] + red[tid * 2 + 1] + b2[0];
            unsigned nz = rnz[tid * 2] | rnz[tid * 2 + 1];
            g_scores[bm0 + tid] = nz ? s : NEG_BIG;
        }

        // --- streaming zero-fill of this tile's output frames ---
        {
            float4 z = make_float4(0.f, 0.f, 0.f, 0.f);
            float4* ob = o4 + (size_t)bm0 * 128;
#pragma unroll
            for (int i = 0; i < 32; i++) __stcs(&ob[tid + i * 256], z);
        }
    }
}

// ---------------------------------------------------------------------------
// Kernel B: exact top-k per row via histogram select.
// ---------------------------------------------------------------------------
__global__ void topk_kernel(const int* kptr) {
    __shared__ int hist[2048];
    __shared__ int sufb[2048];
    __shared__ unsigned long long cand[2048];
    __shared__ int sc4[4];   // [0]=nsel [1]=ncand [2]=bstar [3]=kprime

    const int row = blockIdx.x;
    const int tid = threadIdx.x;
    const float* sc = g_scores + row * 2048;

    int kk = (kptr != nullptr) ? kptr[0] : 64;
    if (kk < 1) kk = 1;
    if (kk > 2048) kk = 2048;

    hist[tid] = 0; hist[tid + 1024] = 0;
    if (tid < 4) sc4[tid] = 0;
    __syncthreads();

    unsigned key[2];
#pragma unroll
    for (int s = 0; s < 2; s++) {
        int t = tid + s * 1024;
        unsigned u = __float_as_uint(sc[t]);
        key[s] = (u & 0x80000000u) ? ~u : (u | 0x80000000u);
        atomicAdd(&hist[key[s] >> 21], 1);
    }
    __syncthreads();

    // inclusive suffix scan over 2048 bins (ping-pong Hillis-Steele)
    int* cur = hist;
    int* nxt = sufb;
    for (int s = 1; s < 2048; s <<= 1) {
#pragma unroll
        for (int q = 0; q < 2; q++) {
            int b = tid + q * 1024;
            nxt[b] = cur[b] + ((b + s < 2048) ? cur[b + s] : 0);
        }
        __syncthreads();
        int* tmp = cur; cur = nxt; nxt = tmp;
    }

    // find threshold bin: suf[b] >= kk and (b==2047 or suf[b+1] < kk)
#pragma unroll
    for (int q = 0; q < 2; q++) {
        int b = tid + q * 1024;
        int above = (b == 2047) ? 0 : cur[b + 1];
        if (cur[b] >= kk && above < kk) {
            sc4[2] = b;
            sc4[3] = kk - above;
        }
    }
    __syncthreads();
    const int bstar = sc4[2];
    const int kprime = sc4[3];

    // pass 2: emit definite selections; collect threshold-bin candidates
#pragma unroll
    for (int s = 0; s < 2; s++) {
        int t = tid + s * 1024;
        int b = key[s] >> 21;
        if (b > bstar) {
            int pos = atomicAdd(&sc4[0], 1);
            g_sel[row * kk + pos] = row * 2048 + t;
        } else if (b == bstar) {
            int c = atomicAdd(&sc4[1], 1);
            // 64-bit tie-break key: (low 21 score bits, then smaller index),
            // bit0=1 marks real entries (pad = 0 sorts below all).
            cand[c] = (((unsigned long long)(key[s] & 0x1FFFFFu)) << 13)
                    | ((unsigned long long)(2047 - t) << 2) | 1ull;
        }
    }
    __syncthreads();

    const int ncand = sc4[1];
    const int nsel = sc4[0];           // == kk - kprime
    int C2 = 1;
    while (C2 < ncand) C2 <<= 1;

    // pad and bitonic-sort C2 candidates ascending
#pragma unroll
    for (int s = 0; s < 2; s++) {
        int i = tid + s * 1024;
        if (i >= ncand && i < C2) cand[i] = 0ull;
    }
    __syncthreads();
    for (int k = 2; k <= C2; k <<= 1) {
        for (int j = k >> 1; j > 0; j >>= 1) {
#pragma unroll
            for (int s = 0; s < 2; s++) {
                int i = tid + s * 1024;
                int l = i ^ j;
                if (i < C2 && l > i) {
                    unsigned long long a = cand[i], b = cand[l];
                    bool up = ((i & k) == 0);
                    if ((a > b) == up) { cand[i] = b; cand[l] = a; }
                }
            }
            __syncthreads();
        }
    }

    // top k' of the candidates complete the selection
#pragma unroll
    for (int s = 0; s < 2; s++) {
        int i = tid + s * 1024;
        if (i >= C2 - kprime && i < C2) {
            int t = 2047 - (int)((cand[i] >> 2) & 2047ull);
            g_sel[row * kk + nsel + (i - (C2 - kprime))] = row * 2048 + t;
        }
    }
}

// ---------------------------------------------------------------------------
// Kernel C: gather — copy only selected frames (out already zero-filled).
// ---------------------------------------------------------------------------
__global__ void gather_kernel(const float* __restrict__ x,
                              float* __restrict__ out, const int* kptr) {
    int kk = (kptr != nullptr) ? kptr[0] : 64;
    if (kk < 1) kk = 1;
    if (kk > 2048) kk = 2048;
    const int total = 32 * kk;
    const float4* x4 = (const float4*)x;
    float4* o4 = (float4*)out;
    for (int slot = blockIdx.x; slot < total; slot += gridDim.x) {
        int fr = g_sel[slot];
        o4[(size_t)fr * 128 + threadIdx.x] = x4[(size_t)fr * 128 + threadIdx.x];
    }
}

extern "C" void kernel_launch(void* const* d_in, const int* in_sizes, int n_in,
                              void* d_out, int out_size) {
    const float* x  = (const float*)d_in[0];
    const float* W1 = (const float*)d_in[1];
    const float* b1 = (const float*)d_in[2];
    const float* W2 = (const float*)d_in[3];
    const float* b2 = (const float*)d_in[4];
    const int* kptr = (n_in >= 6) ? (const int*)d_in[5] : nullptr;

    cudaFuncSetAttribute(score_kernel,
                         cudaFuncAttributeMaxDynamicSharedMemorySize,
                         SMEM_BYTES);
    wprep_kernel<<<64, 256>>>(W1);
    score_kernel<<<444, 256, SMEM_BYTES>>>(x, b1, W2, b2, (float*)d_out);
    topk_kernel<<<32, 1024>>>(kptr);
    gather_kernel<<<2048, 128>>>(x, (float*)d_out, kptr);
}